// round 14
// baseline (speedup 1.0000x reference)
#include <cuda_runtime.h>
#include <math.h>

#define NMAX 8192
#define Hd   512
#define Pd   32
#define Dd   64
#define Kd   100
#define CL   8             // chunk length
#define NBLK (NMAX/64)     // 128 blocks
#define NCH  (NMAX/CL)     // 1024 chunks

typedef unsigned long long u64;

// ---------------- scratch (static device globals; no allocation) -------------
__device__ float  g_W[Dd*Hd];        // V^-1 @ B
__device__ float  g_EA[Dd*Kd];       // E @ alpha
__device__ float  g_G[Dd*Kd];        // V^-1 @ E @ alpha
__device__ float  g_y0[Dd];          // V^-1 @ x0
__device__ float2 g_e[NMAX*Pd];      // per-step complex decay   [n][p]
__device__ float2 g_u[NMAX*Pd];      // per-step complex input   [n][p]
__device__ float4 g_Cc[NCH*Pd];      // per-chunk composite  [c][p]
__device__ float4 g_Bc[NBLK*Pd];     // per-block composite  [b][p]
__device__ unsigned g_sync0 = 0;     // grid barriers (monotone across replays)
__device__ unsigned g_sync1 = 0;

__device__ __forceinline__ float2 cmul(float2 a, float2 b) {
    return make_float2(a.x*b.x - a.y*b.y, a.x*b.y + a.y*b.x);
}
__device__ __forceinline__ float softplus_fast(float x) {
    // __logf arg in [1,2]: cheap MUFU path, abs err ~1e-7
    return x > 0.f ? x + __logf(1.f + __expf(-x)) : __logf(1.f + __expf(x));
}
// packed f32x2 FMA (Blackwell FFMA2; PTX-only pattern)
__device__ __forceinline__ u64 fma2(u64 a, u64 b, u64 c) {
    u64 d;
    asm("fma.rn.f32x2 %0, %1, %2, %3;" : "=l"(d) : "l"(a), "l"(b), "l"(c));
    return d;
}
__device__ __forceinline__ float hadd2(u64 v) {
    float2 f = *reinterpret_cast<float2*>(&v);
    return f.x + f.y;
}

// Device-wide barrier. All NBLK blocks co-resident (grid == 128 <= 148 SMs).
__device__ __forceinline__ void grid_sync(unsigned* ctr) {
    __threadfence();
    __syncthreads();
    if (threadIdx.x == 0) {
        unsigned my = atomicAdd(ctr, 1u);
        unsigned target = (my / (unsigned)NBLK + 1u) * (unsigned)NBLK;
        while (atomicAdd(ctr, 0u) < target) __nanosleep(32);
    }
    __syncthreads();
}

// ---------------- THE kernel: setup -> features -> replay, one launch --------
__global__ void __launch_bounds__(1024, 1)
k_all(const float* __restrict__ times,
      const int*   __restrict__ marks,
      const float* __restrict__ U,
      const float* __restrict__ llr,
      const float* __restrict__ lim,
      const float* __restrict__ Vmat,
      const float* __restrict__ B,
      const float* __restrict__ E,
      const float* __restrict__ alpha,
      const float* __restrict__ gw,
      const float* __restrict__ gb,
      const float* __restrict__ x0,
      float* __restrict__ out, int Nn) {
    __shared__ float S[160*68];      // 43.5 KB, aliased per phase
    int b = blockIdx.x, tid = threadIdx.x;
    int lane = tid & 31, w = tid >> 5;

    // ================= PHASE 0: inverse + W/EA/G/y0 (blocks 0..64) ===========
    if (b <= 64) {
        // register-resident in-place Gauss-Jordan on warps 0..15
        bool act = (w < 16);
        float a0[4], a1[4];
        int r0 = lane, r1 = lane + 32, c0 = (w & 15) * 4;
        if (act) {
            #pragma unroll
            for (int j = 0; j < 4; j++) {
                a0[j] = Vmat[r0*64 + c0 + j];
                a1[j] = Vmat[r1*64 + c0 + j];
            }
        }
        float* colbuf = S + 4160;    // [2][64]
        float* rowbuf = S + 4288;    // [2][68]
        int k = 0;
        for (int ko = 0; ko < 16; ko++) {
            #pragma unroll
            for (int kj = 0; kj < 4; kj++, k++) {
                int par = k & 1;
                int kw  = k >> 2;
                if (act && w == kw) {
                    colbuf[par*64 + r0] = a0[kj];
                    colbuf[par*64 + r1] = a1[kj];
                }
                if (act && lane == (k & 31)) {
                    float* rb = rowbuf + par*68 + c0;
                    if (k < 32) { rb[0]=a0[0]; rb[1]=a0[1]; rb[2]=a0[2]; rb[3]=a0[3]; }
                    else        { rb[0]=a1[0]; rb[1]=a1[1]; rb[2]=a1[2]; rb[3]=a1[3]; }
                }
                __syncthreads();
                if (act) {
                    float p  = rowbuf[par*68 + k];
                    float ip = 1.0f / p;
                    float f0 = (r0 == k) ? (p - 1.f) : colbuf[par*64 + r0];
                    float f1 = (r1 == k) ? (p - 1.f) : colbuf[par*64 + r1];
                    #pragma unroll
                    for (int j = 0; j < 4; j++) {
                        float pvip = rowbuf[par*68 + c0 + j] * ip;
                        a0[j] = fmaf(-f0, pvip, a0[j]);
                        a1[j] = fmaf(-f1, pvip, a1[j]);
                    }
                    if (w == kw) {
                        a0[kj] = (r0 == k) ? ip : -f0 * ip;
                        a1[kj] = (r1 == k) ? ip : -f1 * ip;
                    }
                }
            }
        }
        __syncthreads();
        if (act) {
            #pragma unroll
            for (int j = 0; j < 4; j++) {
                S[r0*65 + c0 + j] = a0[j];
                S[r1*65 + c0 + j] = a1[j];
            }
        }
        __syncthreads();

        if (b < 64) {
            if (tid < Hd) {
                int h = tid;
                float acc = 0.f;
                #pragma unroll 16
                for (int kk = 0; kk < Dd; kk++)
                    acc = fmaf(S[b*65 + kk], B[kk*Hd + h], acc);
                g_W[b*Hd + h] = acc;
            }
        } else {
            float* sEA = S + 4424;
            for (int i = tid; i < Dd*Kd; i += 1024) {
                int d = i / Kd, kk = i % Kd;
                float acc = 0.f;
                #pragma unroll
                for (int r = 0; r < 32; r++) acc = fmaf(E[d*32 + r], alpha[r*Kd + kk], acc);
                sEA[i]  = acc;
                g_EA[i] = acc;
            }
            __syncthreads();
            for (int i = tid; i < Dd*Kd; i += 1024) {
                int d = i / Kd, kk = i % Kd;
                float acc = 0.f;
                #pragma unroll 16
                for (int j = 0; j < Dd; j++) acc = fmaf(S[d*65 + j], sEA[j*Kd + kk], acc);
                g_G[i] = acc;
            }
            if (tid < Dd) {
                float acc = 0.f;
                #pragma unroll 16
                for (int kk = 0; kk < Dd; kk++) acc = fmaf(S[tid*65 + kk], x0[kk], acc);
                g_y0[tid] = acc;
            }
        }
    }
    grid_sync(&g_sync0);

    // ================= PHASE 1: features GEMM (FFMA2, 2x3 tiles, 32 warps) ====
    {
        float* Us = S;             // [64][68]
        float* Ws = S + 64*68;     // [96][68]
        int n0 = b * 64;
        int tx = lane, ty = w;     // warp = 2 rows, lane = 3 cols

        u64 acc2[2][3];
        #pragma unroll
        for (int i = 0; i < 2; i++)
            #pragma unroll
            for (int j = 0; j < 3; j++) acc2[i][j] = 0ull;

        for (int h0 = 0; h0 < Hd; h0 += 64) {
            __syncthreads();
            {   // U tile: exactly one float4 per thread
                int r = tid >> 4, c4 = tid & 15;
                *(float4*)&Us[r*68 + c4*4] = *(const float4*)&U[(n0 + r)*Hd + h0 + c4*4];
            }
            #pragma unroll
            for (int i = tid; i < 96*16; i += 1024) {
                int r = i >> 4, c4 = i & 15;
                const float* src = (r < 32) ? &gw[r*Hd + h0 + c4*4]
                                            : &g_W[(r-32)*Hd + h0 + c4*4];
                *(float4*)&Ws[r*68 + c4*4] = *(const float4*)src;
            }
            __syncthreads();
            #pragma unroll 8
            for (int h4 = 0; h4 < 64; h4 += 4) {
                ulonglong2 rv[2], cv[3];
                #pragma unroll
                for (int ri = 0; ri < 2; ri++)
                    rv[ri] = *(const ulonglong2*)&Us[(ty*2 + ri)*68 + h4];
                #pragma unroll
                for (int ci = 0; ci < 3; ci++)
                    cv[ci] = *(const ulonglong2*)&Ws[(tx + 32*ci)*68 + h4];
                #pragma unroll
                for (int ri = 0; ri < 2; ri++)
                    #pragma unroll
                    for (int ci = 0; ci < 3; ci++) {
                        acc2[ri][ci] = fma2(rv[ri].x, cv[ci].x, acc2[ri][ci]);
                        acc2[ri][ci] = fma2(rv[ri].y, cv[ci].y, acc2[ri][ci]);
                    }
            }
        }

        __syncthreads();
        float* M = S;  // 64 x 97 (cols 0..31 gate_pre, 32..95 w)
        #pragma unroll
        for (int ri = 0; ri < 2; ri++)
            #pragma unroll
            for (int ci = 0; ci < 3; ci++)
                M[(ty*2 + ri)*97 + (tx + 32*ci)] = hadd2(acc2[ri][ci]);
        __syncthreads();

        {
            int p  = lane;
            float spl = softplus_fast(llr[p]);
            float im  = lim[p];
            float gbp = gb[p];
            #pragma unroll
            for (int q = 0; q < 2; q++) {
                int r = w + q*32;
                int n = n0 + r;
                float tn = times[n];
                float dt = tn - ((n > 0) ? times[n-1] : 0.f);
                float gate = softplus_fast(M[r*97 + p] + gbp);
                float re   = -spl * gate;
                float er = __expf(re * dt);
                float th = im * dt;
                float a = er * __cosf(th);
                float c = er * __sinf(th);
                float denom = re*re + im*im;
                float nr = a - 1.f, ni = c;
                float inv_d = __fdividef(1.f, denom + 1e-12f);
                float qr = (nr*re + ni*im) * inv_d;
                float qi = (ni*re - nr*im) * inv_d;
                if (denom < 1e-8f) { qr = dt; qi = 0.f; }
                float wre = M[r*97 + 32 + 2*p];
                float wim = M[r*97 + 33 + 2*p];
                float pos = (dt > 0.f) ? 1.f : 0.f;
                int   mk  = marks[n];
                float ure = (qr*wre - qi*wim) * pos + g_G[(2*p)*Kd + mk];
                float uim = (qr*wim + qi*wre) * pos + g_G[(2*p+1)*Kd + mk];
                g_e[n*Pd + p] = make_float2(a, c);
                g_u[n*Pd + p] = make_float2(ure, uim);
            }
        }

        __syncthreads();
        float4* ccs = (float4*)S;
        if (w < 8) {
            int base = n0 + w * 8;
            float2 Ecomp = make_float2(1.f, 0.f);
            float2 Ucomp = make_float2(0.f, 0.f);
            #pragma unroll
            for (int i = 0; i < CL; i++) {
                float2 e = g_e[(base + i)*Pd + lane];
                float2 u = g_u[(base + i)*Pd + lane];
                Ucomp = cmul(e, Ucomp); Ucomp.x += u.x; Ucomp.y += u.y;
                Ecomp = cmul(e, Ecomp);
            }
            float4 f4 = make_float4(Ecomp.x, Ecomp.y, Ucomp.x, Ucomp.y);
            g_Cc[(b*8 + w)*Pd + lane] = f4;
            ccs[w*32 + lane] = f4;
        }
        __syncthreads();
        if (tid < 32) {
            int p = tid;
            float2 Ecb = make_float2(1.f, 0.f);
            float2 Uvb = make_float2(0.f, 0.f);
            #pragma unroll
            for (int w2 = 0; w2 < 8; w2++) {
                float4 f4 = ccs[w2*32 + p];
                float2 fe = make_float2(f4.x, f4.y);
                float2 fu = make_float2(f4.z, f4.w);
                float2 t = cmul(fe, Uvb);
                Uvb.x = t.x + fu.x; Uvb.y = t.y + fu.y;
                Ecb = cmul(fe, Ecb);
            }
            g_Bc[b*Pd + p] = make_float4(Ecb.x, Ecb.y, Uvb.x, Uvb.y);
        }
    }
    grid_sync(&g_sync1);

    // ================= PHASE 2: replay + output (FFMA2 matvec) ================
    {
        float*  Vs  = S;                       // [64][68]
        float*  Ys  = S + 4352;                // [64][68]
        float4* seg = (float4*)(S + 8704);     // [16][32]
        float2* Tm  = (float2*)(S + 10752);    // [32]
        int*    mks = (int*)(S + 10816);       // [64]
        int n0 = b * 64;

        for (int i = tid; i < Dd*Dd; i += 1024) {
            int r = i >> 6, cc = i & 63;
            Vs[r*68 + cc] = Vmat[i];
        }
        if (tid < 64) mks[tid] = marks[n0 + tid];

        // prefix over prior block-composites [0, b), 16 warp segments
        if (w < 16) {
            float2 Ecb = make_float2(1.f, 0.f);
            float2 Uvb = make_float2(0.f, 0.f);
            int L = (b + 15) >> 4;
            if (L > 0) {
                int s0 = w * L;
                int s1 = s0 + L; if (s1 > b) s1 = b;
                for (int j = s0; j < s1; j++) {
                    float4 f4 = g_Bc[j*Pd + lane];
                    float2 fe = make_float2(f4.x, f4.y);
                    float2 fu = make_float2(f4.z, f4.w);
                    float2 t = cmul(fe, Uvb);
                    Uvb.x = t.x + fu.x; Uvb.y = t.y + fu.y;
                    Ecb = cmul(fe, Ecb);
                }
            }
            seg[w*32 + lane] = make_float4(Ecb.x, Ecb.y, Uvb.x, Uvb.y);
        }
        __syncthreads();
        if (tid < 32) {
            int p = tid;
            float2 Ecb = make_float2(1.f, 0.f);
            float2 Uvb = make_float2(0.f, 0.f);
            #pragma unroll
            for (int t2 = 0; t2 < 16; t2++) {
                float4 f4 = seg[t2*32 + p];
                float2 fe = make_float2(f4.x, f4.y);
                float2 fu = make_float2(f4.z, f4.w);
                float2 t = cmul(fe, Uvb);
                Uvb.x = t.x + fu.x; Uvb.y = t.y + fu.y;
                Ecb = cmul(fe, Ecb);
            }
            float2 y0p = make_float2(g_y0[2*p], g_y0[2*p + 1]);
            float2 s = cmul(Ecb, y0p);
            s.x += Uvb.x; s.y += Uvb.y;
            Tm[p] = s;
        }
        __syncthreads();

        if (w < 8) {
            float2 z = Tm[lane];
            for (int j = 0; j < w; j++) {
                float4 f4 = g_Cc[(b*8 + j)*Pd + lane];
                float2 fe = make_float2(f4.x, f4.y);
                float2 fu = make_float2(f4.z, f4.w);
                z = cmul(fe, z);
                z.x += fu.x; z.y += fu.y;
            }
            int base = n0 + w * 8;
            #pragma unroll
            for (int i = 0; i < CL; i++) {
                float2 e = g_e[(base + i)*Pd + lane];
                float2 u = g_u[(base + i)*Pd + lane];
                z = cmul(e, z); z.x += u.x; z.y += u.y;
                Ys[(w*8 + i)*68 + 2*lane]     = z.x;
                Ys[(w*8 + i)*68 + 2*lane + 1] = z.y;
            }
        }
        __syncthreads();

        int i  = tid & 63;
        int rq = tid >> 6;          // 0..15: 16 rows in flight
        #pragma unroll
        for (int g = 0; g < 4; g++) {
            int row = g*16 + rq;
            u64 acc2 = 0ull;
            #pragma unroll
            for (int k4 = 0; k4 < 16; k4++) {
                ulonglong2 v2 = *(const ulonglong2*)&Vs[i*68 + k4*4];
                ulonglong2 y2 = *(const ulonglong2*)&Ys[row*68 + k4*4];
                acc2 = fma2(v2.x, y2.x, acc2);
                acc2 = fma2(v2.y, y2.y, acc2);
            }
            float acc = hadd2(acc2);
            int n  = n0 + row;
            int mk = mks[row];
            out[n*Dd + i]         = acc;
            out[Nn*Dd + n*Dd + i] = acc - g_EA[i*Kd + mk];
        }
    }
}

// ---------------- launch ------------------------------------------------------
extern "C" void kernel_launch(void* const* d_in, const int* in_sizes, int n_in,
                              void* d_out, int out_size) {
    const float* times = (const float*)d_in[0];
    const int*   marks = (const int*)  d_in[1];
    const float* u     = (const float*)d_in[2];
    const float* llr   = (const float*)d_in[3];
    const float* lim   = (const float*)d_in[4];
    const float* V     = (const float*)d_in[5];
    const float* B     = (const float*)d_in[6];
    const float* E     = (const float*)d_in[7];
    const float* alpha = (const float*)d_in[8];
    const float* gw    = (const float*)d_in[9];
    const float* gb    = (const float*)d_in[10];
    const float* x0    = (const float*)d_in[11];
    float* out = (float*)d_out;

    int Nn = in_sizes[0];          // 8192

    k_all<<<NBLK, 1024>>>(times, marks, u, llr, lim, V, B, E, alpha, gw, gb, x0,
                          out, Nn);
}

// round 15
// speedup vs baseline: 1.2485x; 1.2485x over previous
#include <cuda_runtime.h>
#include <math.h>

#define NMAX 8192
#define Hd   512
#define Pd   32
#define Dd   64
#define Kd   100
#define CL   8             // chunk length
#define NBLK (NMAX/64)     // 128 blocks
#define NCH  (NMAX/CL)     // 1024 chunks

typedef unsigned long long u64;

// ---------------- scratch (static device globals; no allocation) -------------
__device__ float  g_W[Dd*Hd];        // V^-1 @ B
__device__ float  g_EA[Dd*Kd];       // E @ alpha
__device__ float  g_G[Dd*Kd];        // V^-1 @ E @ alpha
__device__ float  g_y0[Dd];          // V^-1 @ x0
__device__ float2 g_e[NMAX*Pd];      // per-step complex decay   [n][p]
__device__ float2 g_u[NMAX*Pd];      // per-step complex input   [n][p]
__device__ float4 g_Cc[NCH*Pd];      // per-chunk composite  [c][p]
__device__ float4 g_Bc[NBLK*Pd];     // per-block composite  [b][p]
__device__ unsigned g_sync0 = 0;     // grid barriers (monotone across replays)
__device__ unsigned g_sync1 = 0;

__device__ __forceinline__ float2 cmul(float2 a, float2 b) {
    return make_float2(a.x*b.x - a.y*b.y, a.x*b.y + a.y*b.x);
}
__device__ __forceinline__ float softplus_fast(float x) {
    // __logf arg in [1,2]: MUFU path, abs err ~1e-7
    return x > 0.f ? x + __logf(1.f + __expf(-x)) : __logf(1.f + __expf(x));
}
// packed f32x2 FMA (Blackwell FFMA2; PTX-only pattern)
__device__ __forceinline__ u64 fma2(u64 a, u64 b, u64 c) {
    u64 d;
    asm("fma.rn.f32x2 %0, %1, %2, %3;" : "=l"(d) : "l"(a), "l"(b), "l"(c));
    return d;
}
__device__ __forceinline__ float hadd2(u64 v) {
    float2 f = *reinterpret_cast<float2*>(&v);
    return f.x + f.y;
}

// Device-wide barrier. All NBLK blocks co-resident (grid == 128 <= 148 SMs).
__device__ __forceinline__ void grid_sync(unsigned* ctr) {
    __threadfence();
    __syncthreads();
    if (threadIdx.x == 0) {
        unsigned my = atomicAdd(ctr, 1u);
        unsigned target = (my / (unsigned)NBLK + 1u) * (unsigned)NBLK;
        while (atomicAdd(ctr, 0u) < target) __nanosleep(32);
    }
    __syncthreads();
}

// ---------------- THE kernel: setup -> features -> replay, one launch --------
__global__ void __launch_bounds__(512, 1)
k_all(const float* __restrict__ times,
      const int*   __restrict__ marks,
      const float* __restrict__ U,
      const float* __restrict__ llr,
      const float* __restrict__ lim,
      const float* __restrict__ Vmat,
      const float* __restrict__ B,
      const float* __restrict__ E,
      const float* __restrict__ alpha,
      const float* __restrict__ gw,
      const float* __restrict__ gb,
      const float* __restrict__ x0,
      float* __restrict__ out, int Nn) {
    __shared__ float S[160*68];      // 43.5 KB, aliased per phase
    int b = blockIdx.x, tid = threadIdx.x;
    int lane = tid & 31, w = tid >> 5;

    // ================= PHASE 0: inverse + W/EA/G/y0 (blocks 0..64) ===========
    if (b <= 64) {
        // register-resident in-place Gauss-Jordan (no pivoting; V ~ I)
        float a0[4], a1[4];
        int r0 = lane, r1 = lane + 32, c0 = w * 4;
        #pragma unroll
        for (int j = 0; j < 4; j++) {
            a0[j] = Vmat[r0*64 + c0 + j];
            a1[j] = Vmat[r1*64 + c0 + j];
        }
        float* colbuf = S + 4160;    // [2][64]
        float* rowbuf = S + 4288;    // [2][68]
        int k = 0;
        for (int ko = 0; ko < 16; ko++) {
            #pragma unroll
            for (int kj = 0; kj < 4; kj++, k++) {
                int par = k & 1;
                int kw  = k >> 2;
                if (w == kw) {
                    colbuf[par*64 + r0] = a0[kj];
                    colbuf[par*64 + r1] = a1[kj];
                }
                if (lane == (k & 31)) {
                    float* rb = rowbuf + par*68 + c0;
                    if (k < 32) { rb[0]=a0[0]; rb[1]=a0[1]; rb[2]=a0[2]; rb[3]=a0[3]; }
                    else        { rb[0]=a1[0]; rb[1]=a1[1]; rb[2]=a1[2]; rb[3]=a1[3]; }
                }
                __syncthreads();
                float p  = rowbuf[par*68 + k];
                float ip = 1.0f / p;
                float f0 = (r0 == k) ? (p - 1.f) : colbuf[par*64 + r0];
                float f1 = (r1 == k) ? (p - 1.f) : colbuf[par*64 + r1];
                #pragma unroll
                for (int j = 0; j < 4; j++) {
                    float pvip = rowbuf[par*68 + c0 + j] * ip;
                    a0[j] = fmaf(-f0, pvip, a0[j]);
                    a1[j] = fmaf(-f1, pvip, a1[j]);
                }
                if (w == kw) {
                    a0[kj] = (r0 == k) ? ip : -f0 * ip;
                    a1[kj] = (r1 == k) ? ip : -f1 * ip;
                }
            }
        }
        __syncthreads();
        #pragma unroll
        for (int j = 0; j < 4; j++) {
            S[r0*65 + c0 + j] = a0[j];
            S[r1*65 + c0 + j] = a1[j];
        }
        __syncthreads();

        if (b < 64) {
            int h = tid;
            float acc = 0.f;
            #pragma unroll 16
            for (int kk = 0; kk < Dd; kk++)
                acc = fmaf(S[b*65 + kk], B[kk*Hd + h], acc);
            g_W[b*Hd + h] = acc;
        } else {
            float* sEA = S + 4424;
            for (int i = tid; i < Dd*Kd; i += 512) {
                int d = i / Kd, kk = i % Kd;
                float acc = 0.f;
                #pragma unroll
                for (int r = 0; r < 32; r++) acc = fmaf(E[d*32 + r], alpha[r*Kd + kk], acc);
                sEA[i]  = acc;
                g_EA[i] = acc;
            }
            __syncthreads();
            for (int i = tid; i < Dd*Kd; i += 512) {
                int d = i / Kd, kk = i % Kd;
                float acc = 0.f;
                #pragma unroll 16
                for (int j = 0; j < Dd; j++) acc = fmaf(S[d*65 + j], sEA[j*Kd + kk], acc);
                g_G[i] = acc;
            }
            if (tid < Dd) {
                float acc = 0.f;
                #pragma unroll 16
                for (int kk = 0; kk < Dd; kk++) acc = fmaf(S[tid*65 + kk], x0[kk], acc);
                g_y0[tid] = acc;
            }
        }
    }
    grid_sync(&g_sync0);

    // ================= PHASE 1: features GEMM (FFMA2) + transcendentals ======
    {
        float* Us = S;             // [64][68]
        float* Ws = S + 64*68;     // [96][68]
        int n0 = b * 64;
        int tx = lane, ty = w;

        u64 acc2[4][3];
        #pragma unroll
        for (int i = 0; i < 4; i++)
            #pragma unroll
            for (int j = 0; j < 3; j++) acc2[i][j] = 0ull;

        for (int h0 = 0; h0 < Hd; h0 += 64) {
            __syncthreads();
            #pragma unroll
            for (int i = tid; i < 64*16; i += 512) {
                int r = i >> 4, c4 = i & 15;
                *(float4*)&Us[r*68 + c4*4] = *(const float4*)&U[(n0 + r)*Hd + h0 + c4*4];
            }
            #pragma unroll
            for (int i = tid; i < 96*16; i += 512) {
                int r = i >> 4, c4 = i & 15;
                const float* src = (r < 32) ? &gw[r*Hd + h0 + c4*4]
                                            : &g_W[(r-32)*Hd + h0 + c4*4];
                *(float4*)&Ws[r*68 + c4*4] = *(const float4*)src;
            }
            __syncthreads();
            #pragma unroll 8
            for (int h4 = 0; h4 < 64; h4 += 4) {
                ulonglong2 rv[4], cv[3];
                #pragma unroll
                for (int ri = 0; ri < 4; ri++)
                    rv[ri] = *(const ulonglong2*)&Us[(ty*4 + ri)*68 + h4];
                #pragma unroll
                for (int ci = 0; ci < 3; ci++)
                    cv[ci] = *(const ulonglong2*)&Ws[(tx + 32*ci)*68 + h4];
                #pragma unroll
                for (int ri = 0; ri < 4; ri++)
                    #pragma unroll
                    for (int ci = 0; ci < 3; ci++) {
                        acc2[ri][ci] = fma2(rv[ri].x, cv[ci].x, acc2[ri][ci]);
                        acc2[ri][ci] = fma2(rv[ri].y, cv[ci].y, acc2[ri][ci]);
                    }
            }
        }

        __syncthreads();
        float* M = S;  // 64 x 97 (cols 0..31 gate_pre, 32..95 w)
        #pragma unroll
        for (int ri = 0; ri < 4; ri++)
            #pragma unroll
            for (int ci = 0; ci < 3; ci++)
                M[(ty*4 + ri)*97 + (tx + 32*ci)] = hadd2(acc2[ri][ci]);
        __syncthreads();

        {
            int p  = lane;
            int r0 = w;
            float spl = softplus_fast(llr[p]);
            float im  = lim[p];
            float gbp = gb[p];
            #pragma unroll
            for (int q = 0; q < 4; q++) {
                int r = r0 + q*16;
                int n = n0 + r;
                float tn = times[n];
                float dt = tn - ((n > 0) ? times[n-1] : 0.f);
                float gate = softplus_fast(M[r*97 + p] + gbp);
                float re   = -spl * gate;
                float er = __expf(re * dt);
                float th = im * dt;
                float a = er * __cosf(th);
                float c = er * __sinf(th);
                float denom = re*re + im*im;
                float nr = a - 1.f, ni = c;
                float inv_d = __fdividef(1.f, denom + 1e-12f);
                float qr = (nr*re + ni*im) * inv_d;
                float qi = (ni*re - nr*im) * inv_d;
                if (denom < 1e-8f) { qr = dt; qi = 0.f; }
                float wre = M[r*97 + 32 + 2*p];
                float wim = M[r*97 + 33 + 2*p];
                float pos = (dt > 0.f) ? 1.f : 0.f;
                int   mk  = marks[n];
                float ure = (qr*wre - qi*wim) * pos + g_G[(2*p)*Kd + mk];
                float uim = (qr*wim + qi*wre) * pos + g_G[(2*p+1)*Kd + mk];
                g_e[n*Pd + p] = make_float2(a, c);
                g_u[n*Pd + p] = make_float2(ure, uim);
            }
        }

        __syncthreads();
        float4* ccs = (float4*)S;
        if (w < 8) {
            int base = n0 + w * 8;
            // MLP-8 prefetch: all 16 loads issued before the dependent chain
            float2 ee[CL], uu[CL];
            #pragma unroll
            for (int i = 0; i < CL; i++) {
                ee[i] = g_e[(base + i)*Pd + lane];
                uu[i] = g_u[(base + i)*Pd + lane];
            }
            float2 Ecomp = make_float2(1.f, 0.f);
            float2 Ucomp = make_float2(0.f, 0.f);
            #pragma unroll
            for (int i = 0; i < CL; i++) {
                Ucomp = cmul(ee[i], Ucomp); Ucomp.x += uu[i].x; Ucomp.y += uu[i].y;
                Ecomp = cmul(ee[i], Ecomp);
            }
            float4 f4 = make_float4(Ecomp.x, Ecomp.y, Ucomp.x, Ucomp.y);
            g_Cc[(b*8 + w)*Pd + lane] = f4;
            ccs[w*32 + lane] = f4;
        }
        __syncthreads();
        if (tid < 32) {
            int p = tid;
            float2 Ecb = make_float2(1.f, 0.f);
            float2 Uvb = make_float2(0.f, 0.f);
            #pragma unroll
            for (int w2 = 0; w2 < 8; w2++) {
                float4 f4 = ccs[w2*32 + p];
                float2 fe = make_float2(f4.x, f4.y);
                float2 fu = make_float2(f4.z, f4.w);
                float2 t = cmul(fe, Uvb);
                Uvb.x = t.x + fu.x; Uvb.y = t.y + fu.y;
                Ecb = cmul(fe, Ecb);
            }
            g_Bc[b*Pd + p] = make_float4(Ecb.x, Ecb.y, Uvb.x, Uvb.y);
        }
    }
    grid_sync(&g_sync1);

    // ================= PHASE 2: replay + output (FFMA2 matvec) ================
    {
        float*  Vs  = S;                       // [64][68]
        float*  Ys  = S + 4352;                // [64][68]
        float4* seg = (float4*)(S + 8704);     // [16][32]
        float2* Tm  = (float2*)(S + 10752);    // [32]
        int*    mks = (int*)(S + 10816);       // [64]
        int n0 = b * 64;

        for (int i = tid; i < Dd*Dd; i += 512) {
            int r = i >> 6, cc = i & 63;
            Vs[r*68 + cc] = Vmat[i];
        }
        if (tid < 64) mks[tid] = marks[n0 + tid];

        // prefix over prior block-composites [0, b), 16 warp segments
        {
            float2 Ecb = make_float2(1.f, 0.f);
            float2 Uvb = make_float2(0.f, 0.f);
            int L = (b + 15) >> 4;
            if (L > 0) {
                int s0 = w * L;
                int s1 = s0 + L; if (s1 > b) s1 = b;
                for (int j = s0; j < s1; j++) {
                    float4 f4 = g_Bc[j*Pd + lane];
                    float2 fe = make_float2(f4.x, f4.y);
                    float2 fu = make_float2(f4.z, f4.w);
                    float2 t = cmul(fe, Uvb);
                    Uvb.x = t.x + fu.x; Uvb.y = t.y + fu.y;
                    Ecb = cmul(fe, Ecb);
                }
            }
            seg[w*32 + lane] = make_float4(Ecb.x, Ecb.y, Uvb.x, Uvb.y);
        }
        __syncthreads();
        if (tid < 32) {
            int p = tid;
            float2 Ecb = make_float2(1.f, 0.f);
            float2 Uvb = make_float2(0.f, 0.f);
            #pragma unroll
            for (int t2 = 0; t2 < 16; t2++) {
                float4 f4 = seg[t2*32 + p];
                float2 fe = make_float2(f4.x, f4.y);
                float2 fu = make_float2(f4.z, f4.w);
                float2 t = cmul(fe, Uvb);
                Uvb.x = t.x + fu.x; Uvb.y = t.y + fu.y;
                Ecb = cmul(fe, Ecb);
            }
            float2 y0p = make_float2(g_y0[2*p], g_y0[2*p + 1]);
            float2 s = cmul(Ecb, y0p);
            s.x += Uvb.x; s.y += Uvb.y;
            Tm[p] = s;
        }
        __syncthreads();

        if (w < 8) {
            // prefetch own-chunk prior composites (<=7) and the 8-step e/u
            float4 cpre[7];
            #pragma unroll
            for (int j = 0; j < 7; j++)
                if (j < w) cpre[j] = g_Cc[(b*8 + j)*Pd + lane];
            int base = n0 + w * 8;
            float2 ee[CL], uu[CL];
            #pragma unroll
            for (int i = 0; i < CL; i++) {
                ee[i] = g_e[(base + i)*Pd + lane];
                uu[i] = g_u[(base + i)*Pd + lane];
            }
            float2 z = Tm[lane];
            #pragma unroll
            for (int j = 0; j < 7; j++) {
                if (j < w) {
                    float2 fe = make_float2(cpre[j].x, cpre[j].y);
                    float2 fu = make_float2(cpre[j].z, cpre[j].w);
                    z = cmul(fe, z);
                    z.x += fu.x; z.y += fu.y;
                }
            }
            #pragma unroll
            for (int i = 0; i < CL; i++) {
                z = cmul(ee[i], z); z.x += uu[i].x; z.y += uu[i].y;
                Ys[(w*8 + i)*68 + 2*lane]     = z.x;
                Ys[(w*8 + i)*68 + 2*lane + 1] = z.y;
            }
        }
        __syncthreads();

        int i  = tid & 63;
        int rq = tid >> 6;
        #pragma unroll
        for (int g = 0; g < 8; g++) {
            int row = g*8 + rq;
            u64 acc2 = 0ull;
            #pragma unroll
            for (int k4 = 0; k4 < 16; k4++) {
                ulonglong2 v2 = *(const ulonglong2*)&Vs[i*68 + k4*4];
                ulonglong2 y2 = *(const ulonglong2*)&Ys[row*68 + k4*4];
                acc2 = fma2(v2.x, y2.x, acc2);
                acc2 = fma2(v2.y, y2.y, acc2);
            }
            float acc = hadd2(acc2);
            int n  = n0 + row;
            int mk = mks[row];
            out[n*Dd + i]         = acc;
            out[Nn*Dd + n*Dd + i] = acc - g_EA[i*Kd + mk];
        }
    }
}

// ---------------- launch ------------------------------------------------------
extern "C" void kernel_launch(void* const* d_in, const int* in_sizes, int n_in,
                              void* d_out, int out_size) {
    const float* times = (const float*)d_in[0];
    const int*   marks = (const int*)  d_in[1];
    const float* u     = (const float*)d_in[2];
    const float* llr   = (const float*)d_in[3];
    const float* lim   = (const float*)d_in[4];
    const float* V     = (const float*)d_in[5];
    const float* B     = (const float*)d_in[6];
    const float* E     = (const float*)d_in[7];
    const float* alpha = (const float*)d_in[8];
    const float* gw    = (const float*)d_in[9];
    const float* gb    = (const float*)d_in[10];
    const float* x0    = (const float*)d_in[11];
    float* out = (float*)d_out;

    int Nn = in_sizes[0];          // 8192

    k_all<<<NBLK, 512>>>(times, marks, u, llr, lim, V, B, E, alpha, gw, gb, x0,
                         out, Nn);
}

// round 17
// speedup vs baseline: 1.2662x; 1.0141x over previous
#include <cuda_runtime.h>
#include <cstdint>
#include <math.h>

#define NMAX 8192
#define Hd   512
#define Pd   32
#define Dd   64
#define Kd   100
#define CL   8             // chunk length
#define NBLK (NMAX/64)     // 128 blocks
#define NCH  (NMAX/CL)     // 1024 chunks

typedef unsigned long long u64;
typedef unsigned int u32;

// dynamic smem layout (floats):
//  [0,4096)        se : 64x32 float2 (per-step decay, this block)
//  [4096,8192)     su : 64x32 float2 (per-step input)
//  [8192,19072)    buf0 : 160x68 tile buffer / phase-0 workspace / phase-2 Vs..
//  [19072,29952)   buf1 : 160x68 tile buffer / ccs (chunk composites)
#define SMEM_FLOATS 29952
#define SMEM_BYTES  (SMEM_FLOATS*4)

// ---------------- scratch (static device globals; no allocation) -------------
__device__ float  g_W[Dd*Hd];        // V^-1 @ B
__device__ float  g_EA[Dd*Kd];       // E @ alpha
__device__ float  g_G[Dd*Kd];        // V^-1 @ E @ alpha
__device__ float  g_y0[Dd];          // V^-1 @ x0
__device__ float4 g_Bc[NBLK*Pd];     // per-block composite  [b][p]
__device__ unsigned g_sync0 = 0;     // grid barriers (monotone across replays)
__device__ unsigned g_sync1 = 0;

__device__ __forceinline__ float2 cmul(float2 a, float2 b) {
    return make_float2(a.x*b.x - a.y*b.y, a.x*b.y + a.y*b.x);
}
__device__ __forceinline__ float softplus_fast(float x) {
    return x > 0.f ? x + __logf(1.f + __expf(-x)) : __logf(1.f + __expf(x));
}
// packed f32x2 FMA (Blackwell FFMA2; PTX-only pattern)
__device__ __forceinline__ u64 fma2(u64 a, u64 b, u64 c) {
    u64 d;
    asm("fma.rn.f32x2 %0, %1, %2, %3;" : "=l"(d) : "l"(a), "l"(b), "l"(c));
    return d;
}
__device__ __forceinline__ float hadd2(u64 v) {
    float2 f = *reinterpret_cast<float2*>(&v);
    return f.x + f.y;
}
// cp.async 16B global->shared
__device__ __forceinline__ void cp16(u32 smem_dst, const void* gsrc) {
    asm volatile("cp.async.cg.shared.global [%0], [%1], 16;"
                 :: "r"(smem_dst), "l"(gsrc));
}
__device__ __forceinline__ void cp_commit() {
    asm volatile("cp.async.commit_group;" ::: "memory");
}
__device__ __forceinline__ void cp_wait0() {
    asm volatile("cp.async.wait_group 0;" ::: "memory");
}

// Device-wide barrier. All NBLK blocks co-resident (grid == 128 <= 148 SMs).
__device__ __forceinline__ void grid_sync(unsigned* ctr) {
    __threadfence();
    __syncthreads();
    if (threadIdx.x == 0) {
        unsigned my = atomicAdd(ctr, 1u);
        unsigned target = (my / (unsigned)NBLK + 1u) * (unsigned)NBLK;
        while (atomicAdd(ctr, 0u) < target) __nanosleep(32);
    }
    __syncthreads();
}

// ---------------- THE kernel: setup -> features -> replay, one launch --------
__global__ void __launch_bounds__(512, 1)
k_all(const float* __restrict__ times,
      const int*   __restrict__ marks,
      const float* __restrict__ U,
      const float* __restrict__ llr,
      const float* __restrict__ lim,
      const float* __restrict__ Vmat,
      const float* __restrict__ B,
      const float* __restrict__ E,
      const float* __restrict__ alpha,
      const float* __restrict__ gw,
      const float* __restrict__ gb,
      const float* __restrict__ x0,
      float* __restrict__ out, int Nn) {
    extern __shared__ float SS[];
    float2* se  = (float2*)SS;             // [64*32]
    float2* su  = (float2*)(SS + 4096);    // [64*32]
    float*  buf0 = SS + 8192;              // 10880 floats
    float*  buf1 = SS + 19072;             // 10880 floats

    int b = blockIdx.x, tid = threadIdx.x;
    int lane = tid & 31, w = tid >> 5;
    int n0 = b * 64;

    // ================= PHASE 0: inverse + W/EA/G/y0 (blocks 0..64) ===========
    if (b <= 64) {
        float* S = buf0;
        // register-resident in-place Gauss-Jordan (no pivoting; V ~ I)
        float a0[4], a1[4];
        int r0 = lane, r1 = lane + 32, c0 = w * 4;
        #pragma unroll
        for (int j = 0; j < 4; j++) {
            a0[j] = Vmat[r0*64 + c0 + j];
            a1[j] = Vmat[r1*64 + c0 + j];
        }
        float* colbuf = S + 4160;    // [2][64]
        float* rowbuf = S + 4288;    // [2][68]
        int k = 0;
        for (int ko = 0; ko < 16; ko++) {
            #pragma unroll
            for (int kj = 0; kj < 4; kj++, k++) {
                int par = k & 1;
                int kw  = k >> 2;
                if (w == kw) {
                    colbuf[par*64 + r0] = a0[kj];
                    colbuf[par*64 + r1] = a1[kj];
                }
                if (lane == (k & 31)) {
                    float* rb = rowbuf + par*68 + c0;
                    if (k < 32) { rb[0]=a0[0]; rb[1]=a0[1]; rb[2]=a0[2]; rb[3]=a0[3]; }
                    else        { rb[0]=a1[0]; rb[1]=a1[1]; rb[2]=a1[2]; rb[3]=a1[3]; }
                }
                __syncthreads();
                float p  = rowbuf[par*68 + k];
                float ip = 1.0f / p;
                float f0 = (r0 == k) ? (p - 1.f) : colbuf[par*64 + r0];
                float f1 = (r1 == k) ? (p - 1.f) : colbuf[par*64 + r1];
                #pragma unroll
                for (int j = 0; j < 4; j++) {
                    float pvip = rowbuf[par*68 + c0 + j] * ip;
                    a0[j] = fmaf(-f0, pvip, a0[j]);
                    a1[j] = fmaf(-f1, pvip, a1[j]);
                }
                if (w == kw) {
                    a0[kj] = (r0 == k) ? ip : -f0 * ip;
                    a1[kj] = (r1 == k) ? ip : -f1 * ip;
                }
            }
        }
        __syncthreads();
        #pragma unroll
        for (int j = 0; j < 4; j++) {
            S[r0*65 + c0 + j] = a0[j];
            S[r1*65 + c0 + j] = a1[j];
        }
        __syncthreads();

        if (b < 64) {
            int h = tid;
            float acc = 0.f;
            #pragma unroll 16
            for (int kk = 0; kk < Dd; kk++)
                acc = fmaf(S[b*65 + kk], B[kk*Hd + h], acc);
            g_W[b*Hd + h] = acc;
        } else {
            float* sEA = S + 4424;
            for (int i = tid; i < Dd*Kd; i += 512) {
                int d = i / Kd, kk = i % Kd;
                float acc = 0.f;
                #pragma unroll
                for (int r = 0; r < 32; r++) acc = fmaf(E[d*32 + r], alpha[r*Kd + kk], acc);
                sEA[i]  = acc;
                g_EA[i] = acc;
            }
            __syncthreads();
            for (int i = tid; i < Dd*Kd; i += 512) {
                int d = i / Kd, kk = i % Kd;
                float acc = 0.f;
                #pragma unroll 16
                for (int j = 0; j < Dd; j++) acc = fmaf(S[d*65 + j], sEA[j*Kd + kk], acc);
                g_G[i] = acc;
            }
            if (tid < Dd) {
                float acc = 0.f;
                #pragma unroll 16
                for (int kk = 0; kk < Dd; kk++) acc = fmaf(S[tid*65 + kk], x0[kk], acc);
                g_y0[tid] = acc;
            }
        }
    }
    grid_sync(&g_sync0);

    // ================= PHASE 1: pipelined GEMM (cp.async) + transcendentals ==
    {
        int tx = lane, ty = w;

        u64 acc2[4][3];
        #pragma unroll
        for (int i = 0; i < 4; i++)
            #pragma unroll
            for (int j = 0; j < 3; j++) acc2[i][j] = 0ull;

        // prefetch tile 0 into buf0
        {
            float* dst = buf0;
            u32 dA = (u32)__cvta_generic_to_shared(dst);
            u32 dW = (u32)__cvta_generic_to_shared(dst + 4352);
            #pragma unroll
            for (int i = tid; i < 64*16; i += 512) {
                int r = i >> 4, c4 = i & 15;
                cp16(dA + (u32)((r*68 + c4*4)*4), &U[(n0 + r)*Hd + c4*4]);
            }
            #pragma unroll
            for (int i = tid; i < 96*16; i += 512) {
                int r = i >> 4, c4 = i & 15;
                const float* src = (r < 32) ? &gw[r*Hd + c4*4]
                                            : &g_W[(r-32)*Hd + c4*4];
                cp16(dW + (u32)((r*68 + c4*4)*4), src);
            }
            cp_commit();
        }

        for (int t = 0; t < 8; t++) {
            cp_wait0();
            __syncthreads();
            if (t < 7) {
                float* dst = (t & 1) ? buf0 : buf1;   // buffer for tile t+1
                int h0 = (t + 1) * 64;
                u32 dA = (u32)__cvta_generic_to_shared(dst);
                u32 dW = (u32)__cvta_generic_to_shared(dst + 4352);
                #pragma unroll
                for (int i = tid; i < 64*16; i += 512) {
                    int r = i >> 4, c4 = i & 15;
                    cp16(dA + (u32)((r*68 + c4*4)*4), &U[(n0 + r)*Hd + h0 + c4*4]);
                }
                #pragma unroll
                for (int i = tid; i < 96*16; i += 512) {
                    int r = i >> 4, c4 = i & 15;
                    const float* src = (r < 32) ? &gw[r*Hd + h0 + c4*4]
                                                : &g_W[(r-32)*Hd + h0 + c4*4];
                    cp16(dW + (u32)((r*68 + c4*4)*4), src);
                }
                cp_commit();
            }
            float* Us = (t & 1) ? buf1 : buf0;
            float* Ws = Us + 4352;
            #pragma unroll 8
            for (int h4 = 0; h4 < 64; h4 += 4) {
                ulonglong2 rv[4], cv[3];
                #pragma unroll
                for (int ri = 0; ri < 4; ri++)
                    rv[ri] = *(const ulonglong2*)&Us[(ty*4 + ri)*68 + h4];
                #pragma unroll
                for (int ci = 0; ci < 3; ci++)
                    cv[ci] = *(const ulonglong2*)&Ws[(tx + 32*ci)*68 + h4];
                #pragma unroll
                for (int ri = 0; ri < 4; ri++)
                    #pragma unroll
                    for (int ci = 0; ci < 3; ci++) {
                        acc2[ri][ci] = fma2(rv[ri].x, cv[ci].x, acc2[ri][ci]);
                        acc2[ri][ci] = fma2(rv[ri].y, cv[ci].y, acc2[ri][ci]);
                    }
            }
            __syncthreads();
        }

        float* M = buf0;  // 64 x 97 (cols 0..31 gate_pre, 32..95 w); tile7 was buf1
        #pragma unroll
        for (int ri = 0; ri < 4; ri++)
            #pragma unroll
            for (int ci = 0; ci < 3; ci++)
                M[(ty*4 + ri)*97 + (tx + 32*ci)] = hadd2(acc2[ri][ci]);
        __syncthreads();

        {
            int p  = lane;
            int r0 = w;
            float spl = softplus_fast(llr[p]);
            float im  = lim[p];
            float gbp = gb[p];
            #pragma unroll
            for (int q = 0; q < 4; q++) {
                int r = r0 + q*16;
                int n = n0 + r;
                float tn = times[n];
                float dt = tn - ((n > 0) ? times[n-1] : 0.f);
                float gate = softplus_fast(M[r*97 + p] + gbp);
                float re   = -spl * gate;
                float er = __expf(re * dt);
                float th = im * dt;
                float a = er * __cosf(th);
                float c = er * __sinf(th);
                float denom = re*re + im*im;
                float nr = a - 1.f, ni = c;
                float inv_d = __fdividef(1.f, denom + 1e-12f);
                float qr = (nr*re + ni*im) * inv_d;
                float qi = (ni*re - nr*im) * inv_d;
                if (denom < 1e-8f) { qr = dt; qi = 0.f; }
                float wre = M[r*97 + 32 + 2*p];
                float wim = M[r*97 + 33 + 2*p];
                float pos = (dt > 0.f) ? 1.f : 0.f;
                int   mk  = marks[n];
                float ure = (qr*wre - qi*wim) * pos + g_G[(2*p)*Kd + mk];
                float uim = (qr*wim + qi*wre) * pos + g_G[(2*p+1)*Kd + mk];
                se[r*32 + p] = make_float2(a, c);
                su[r*32 + p] = make_float2(ure, uim);
            }
        }

        __syncthreads();
        float4* ccs = (float4*)buf1;    // chunk composites [8][32], persists->phase2
        if (w < 8) {
            float2 Ecomp = make_float2(1.f, 0.f);
            float2 Ucomp = make_float2(0.f, 0.f);
            #pragma unroll
            for (int i = 0; i < CL; i++) {
                float2 e = se[(w*8 + i)*32 + lane];
                float2 u = su[(w*8 + i)*32 + lane];
                Ucomp = cmul(e, Ucomp); Ucomp.x += u.x; Ucomp.y += u.y;
                Ecomp = cmul(e, Ecomp);
            }
            ccs[w*32 + lane] = make_float4(Ecomp.x, Ecomp.y, Ucomp.x, Ucomp.y);
        }
        __syncthreads();
        if (tid < 32) {
            int p = tid;
            float2 Ecb = make_float2(1.f, 0.f);
            float2 Uvb = make_float2(0.f, 0.f);
            #pragma unroll
            for (int w2 = 0; w2 < 8; w2++) {
                float4 f4 = ccs[w2*32 + p];
                float2 fe = make_float2(f4.x, f4.y);
                float2 fu = make_float2(f4.z, f4.w);
                float2 t = cmul(fe, Uvb);
                Uvb.x = t.x + fu.x; Uvb.y = t.y + fu.y;
                Ecb = cmul(fe, Ecb);
            }
            g_Bc[b*Pd + p] = make_float4(Ecb.x, Ecb.y, Uvb.x, Uvb.y);
        }
    }
    grid_sync(&g_sync1);

    // ================= PHASE 2: replay + output (FFMA2 matvec) ================
    {
        float*  Vs  = buf0;                    // [64][68]
        float*  Ys  = buf0 + 4352;             // [64][68]
        float4* seg = (float4*)(buf0 + 8704);  // [16][32]
        float2* Tm  = (float2*)(buf0 + 10752); // [32]
        int*    mks = (int*)(buf0 + 10816);    // [64]
        float4* ccs = (float4*)buf1;           // own chunk composites (phase 1)

        for (int i = tid; i < Dd*Dd; i += 512) {
            int r = i >> 6, cc = i & 63;
            Vs[r*68 + cc] = Vmat[i];
        }
        if (tid < 64) mks[tid] = marks[n0 + tid];

        // prefix over prior block-composites [0, b), 16 warp segments
        {
            float2 Ecb = make_float2(1.f, 0.f);
            float2 Uvb = make_float2(0.f, 0.f);
            int L = (b + 15) >> 4;
            if (L > 0) {
                int s0 = w * L;
                int s1 = s0 + L; if (s1 > b) s1 = b;
                for (int j = s0; j < s1; j++) {
                    float4 f4 = g_Bc[j*Pd + lane];
                    float2 fe = make_float2(f4.x, f4.y);
                    float2 fu = make_float2(f4.z, f4.w);
                    float2 t = cmul(fe, Uvb);
                    Uvb.x = t.x + fu.x; Uvb.y = t.y + fu.y;
                    Ecb = cmul(fe, Ecb);
                }
            }
            seg[w*32 + lane] = make_float4(Ecb.x, Ecb.y, Uvb.x, Uvb.y);
        }
        __syncthreads();
        if (tid < 32) {
            int p = tid;
            float2 Ecb = make_float2(1.f, 0.f);
            float2 Uvb = make_float2(0.f, 0.f);
            #pragma unroll
            for (int t2 = 0; t2 < 16; t2++) {
                float4 f4 = seg[t2*32 + p];
                float2 fe = make_float2(f4.x, f4.y);
                float2 fu = make_float2(f4.z, f4.w);
                float2 t = cmul(fe, Uvb);
                Uvb.x = t.x + fu.x; Uvb.y = t.y + fu.y;
                Ecb = cmul(fe, Ecb);
            }
            float2 y0p = make_float2(g_y0[2*p], g_y0[2*p + 1]);
            float2 s = cmul(Ecb, y0p);
            s.x += Uvb.x; s.y += Uvb.y;
            Tm[p] = s;
        }
        __syncthreads();

        if (w < 8) {
            float2 z = Tm[lane];
            #pragma unroll
            for (int j = 0; j < 7; j++) {
                if (j < w) {
                    float4 f4 = ccs[j*32 + lane];
                    float2 fe = make_float2(f4.x, f4.y);
                    float2 fu = make_float2(f4.z, f4.w);
                    z = cmul(fe, z);
                    z.x += fu.x; z.y += fu.y;
                }
            }
            #pragma unroll
            for (int i = 0; i < CL; i++) {
                float2 e = se[(w*8 + i)*32 + lane];
                float2 u = su[(w*8 + i)*32 + lane];
                z = cmul(e, z); z.x += u.x; z.y += u.y;
                Ys[(w*8 + i)*68 + 2*lane]     = z.x;
                Ys[(w*8 + i)*68 + 2*lane + 1] = z.y;
            }
        }
        __syncthreads();

        int i  = tid & 63;
        int rq = tid >> 6;
        #pragma unroll
        for (int g = 0; g < 8; g++) {
            int row = g*8 + rq;
            u64 acc2 = 0ull;
            #pragma unroll
            for (int k4 = 0; k4 < 16; k4++) {
                ulonglong2 v2 = *(const ulonglong2*)&Vs[i*68 + k4*4];
                ulonglong2 y2 = *(const ulonglong2*)&Ys[row*68 + k4*4];
                acc2 = fma2(v2.x, y2.x, acc2);
                acc2 = fma2(v2.y, y2.y, acc2);
            }
            float acc = hadd2(acc2);
            int n  = n0 + row;
            int mk = mks[row];
            out[n*Dd + i]         = acc;
            out[Nn*Dd + n*Dd + i] = acc - g_EA[i*Kd + mk];
        }
    }
}

// ---------------- launch ------------------------------------------------------
extern "C" void kernel_launch(void* const* d_in, const int* in_sizes, int n_in,
                              void* d_out, int out_size) {
    const float* times = (const float*)d_in[0];
    const int*   marks = (const int*)  d_in[1];
    const float* u     = (const float*)d_in[2];
    const float* llr   = (const float*)d_in[3];
    const float* lim   = (const float*)d_in[4];
    const float* V     = (const float*)d_in[5];
    const float* B     = (const float*)d_in[6];
    const float* E     = (const float*)d_in[7];
    const float* alpha = (const float*)d_in[8];
    const float* gw    = (const float*)d_in[9];
    const float* gb    = (const float*)d_in[10];
    const float* x0    = (const float*)d_in[11];
    float* out = (float*)d_out;

    int Nn = in_sizes[0];          // 8192

    cudaFuncSetAttribute(k_all, cudaFuncAttributeMaxDynamicSharedMemorySize,
                         SMEM_BYTES);
    k_all<<<NBLK, 512, SMEM_BYTES>>>(times, marks, u, llr, lim, V, B, E, alpha,
                                     gw, gb, x0, out, Nn);
}